// round 15
// baseline (speedup 1.0000x reference)
#include <cuda_runtime.h>
#include <math.h>
#include <stdint.h>

#define BB 512
#define DD 512
#define LL 24

#define TR 32               // tile rows (active anchors)
#define TC 64               // tile cols
#define KC 16
#define SPLITS 4
#define KSP (DD / SPLITS)   // 128
#define NCHUNK (KSP / KC)   // 8

// Scratch (device globals — no allocations allowed)
__device__ float        g_part[SPLITS][BB * BB];  // [z][ii_compact * BB + j]
__device__ float        g_norm[BB];
__device__ unsigned int g_lab[BB];
__device__ int          g_act[BB];
__device__ int          g_nact;
__device__ float        g_sum;
__device__ unsigned int g_cnt;
__device__ unsigned int g_done;

// Packed dual-FP32 FMA (Blackwell f32x2; base-family PTX, sm_100+)
#define FMA2(acc, a, b) \
    asm("fma.rn.f32x2 %0, %1, %2, %0;" : "+l"(acc) : "l"(a), "l"(b))
#define PACK_DUP(out, f) \
    asm("mov.b64 %0, {%1, %1};" : "=l"(out) : "r"(__float_as_uint(f)))
#define UNPACK2(lo, hi, in) \
    asm("mov.b64 {%0, %1}, %2;" : "=r"(lo), "=r"(hi) : "l"(in))

// ---------------------------------------------------------------------------
// Kernel 0: prep. Block 0: pack label masks, find active anchors (those with
// >=1 negative), build DETERMINISTIC sorted compact list via ballot scan.
// Blocks 1..32: row norms (16 rows each, warp per row).
// ---------------------------------------------------------------------------
__global__ __launch_bounds__(512) void k_prep(const float* __restrict__ X,
                                              const int* __restrict__ labels) {
    int b = blockIdx.x;
    int tid = threadIdx.x;
    int lane = tid & 31, w = tid >> 5;

    if (b == 0) {
        __shared__ unsigned labs[BB];
        __shared__ int wcount[16];
        unsigned m = 0u;
#pragma unroll
        for (int l = 0; l < LL; ++l)
            if (labels[tid * LL + l] != 0) m |= (1u << l);
        labs[tid] = m;
        g_lab[tid] = m;
        if (tid == 0) { g_sum = 0.0f; g_cnt = 0u; g_done = 0u; }
        __syncthreads();

        bool act = false;
        for (int j = 0; j < BB; ++j)
            if ((labs[j] & m) == 0u) { act = true; break; }

        unsigned bal = __ballot_sync(0xffffffffu, act);
        if (lane == 0) wcount[w] = __popc(bal);
        __syncthreads();
        int base = 0;
        for (int ww = 0; ww < w; ++ww) base += wcount[ww];
        if (act) {
            int r = __popc(bal & ((1u << lane) - 1u));
            g_act[base + r] = tid;
        }
        if (tid == 511) {
            int tot = 0;
            for (int ww = 0; ww < 16; ++ww) tot += wcount[ww];
            g_nact = tot;
        }
    } else {
        int row = (b - 1) * 16 + w;           // blocks 1..32, 16 rows each
        const float4* xr = reinterpret_cast<const float4*>(X + row * DD);
        float s = 0.0f;
#pragma unroll
        for (int t = 0; t < 4; ++t) {
            float4 v = xr[t * 32 + lane];
            s += v.x * v.x + v.y * v.y + v.z * v.z + v.w * v.w;
        }
#pragma unroll
        for (int off = 16; off; off >>= 1)
            s += __shfl_down_sync(0xffffffffu, s, off);
        if (lane == 0) g_norm[row] = s;
    }
}

// ---------------------------------------------------------------------------
// Kernel 1: Gram partials for ACTIVE anchor rows only. Tile 32 (gathered
// active rows) x 64 cols, K-split 4. Grid (8,16,4)=512 slots; slots past
// nact exit immediately (~0.4x survive). Microtile 4 rows (2 pairs) x 4 cols
// = 8 FFMA2/kk, proven staging/prefetch pattern.
// ---------------------------------------------------------------------------
__global__ __launch_bounds__(128) void k_gram(const float* __restrict__ X) {
    int nact = g_nact;
    int rowBase = blockIdx.y * TR;
    if (rowBase >= nact) return;

    __shared__ float As[2][KC][TR + 4];
    __shared__ float Bs[2][KC][TC + 4];

    int tid = threadIdx.x;
    int ty = tid >> 4;          // 0..7  : 4 rows (2 pairs)
    int tx = tid & 15;          // 0..15 : 4 cols
    int colBase = blockIdx.x * TC;
    int z       = blockIdx.z;
    int kBase   = z * KSP;

    // staging: A = 128 float4 (1/thread), B = 256 float4 (2/thread)
    int ar  = tid >> 2;                 // 0..31
    int kg  = (tid & 3) * 4;
    int aidx = rowBase + ar;
    int asrc = (aidx < nact) ? g_act[aidx] : g_act[0];
    const float* Arow  = &X[asrc * DD + kBase];
    const float* Brow0 = &X[(colBase + ar) * DD + kBase];
    const float* Brow1 = &X[(colBase + ar + 32) * DD + kBase];

    unsigned long long acc[2][4];
#pragma unroll
    for (int p = 0; p < 2; ++p)
#pragma unroll
        for (int c = 0; c < 4; ++c) acc[p][c] = 0ull;

    float4 pa  = *reinterpret_cast<const float4*>(&Arow[kg]);
    float4 pb0 = *reinterpret_cast<const float4*>(&Brow0[kg]);
    float4 pb1 = *reinterpret_cast<const float4*>(&Brow1[kg]);

#pragma unroll
    for (int c = 0; c < NCHUNK; ++c) {
        int buf = c & 1;
        As[buf][kg + 0][ar] = pa.x;  As[buf][kg + 1][ar] = pa.y;
        As[buf][kg + 2][ar] = pa.z;  As[buf][kg + 3][ar] = pa.w;
        Bs[buf][kg + 0][ar] = pb0.x; Bs[buf][kg + 1][ar] = pb0.y;
        Bs[buf][kg + 2][ar] = pb0.z; Bs[buf][kg + 3][ar] = pb0.w;
        Bs[buf][kg + 0][ar + 32] = pb1.x; Bs[buf][kg + 1][ar + 32] = pb1.y;
        Bs[buf][kg + 2][ar + 32] = pb1.z; Bs[buf][kg + 3][ar + 32] = pb1.w;
        __syncthreads();

        if (c + 1 < NCHUNK) {
            int ko = (c + 1) * KC;
            pa  = *reinterpret_cast<const float4*>(&Arow[ko + kg]);
            pb0 = *reinterpret_cast<const float4*>(&Brow0[ko + kg]);
            pb1 = *reinterpret_cast<const float4*>(&Brow1[ko + kg]);
        }

#pragma unroll
        for (int kk = 0; kk < KC; ++kk) {
            ulonglong2 a2 =
                *reinterpret_cast<const ulonglong2*>(&As[buf][kk][ty * 4]);
            float4 b4 = *reinterpret_cast<const float4*>(&Bs[buf][kk][tx * 4]);
            unsigned long long B0, B1, B2, B3;
            PACK_DUP(B0, b4.x); PACK_DUP(B1, b4.y);
            PACK_DUP(B2, b4.z); PACK_DUP(B3, b4.w);
            FMA2(acc[0][0], a2.x, B0); FMA2(acc[0][1], a2.x, B1);
            FMA2(acc[0][2], a2.x, B2); FMA2(acc[0][3], a2.x, B3);
            FMA2(acc[1][0], a2.y, B0); FMA2(acc[1][1], a2.y, B1);
            FMA2(acc[1][2], a2.y, B2); FMA2(acc[1][3], a2.y, B3);
        }
        __syncthreads();
    }

    // epilogue: 2 row-pairs x 4 cols (compacted row index ii)
    int gj = colBase + tx * 4;
#pragma unroll
    for (int p = 0; p < 2; ++p) {
        unsigned lo[4], hi[4];
#pragma unroll
        for (int c = 0; c < 4; ++c) UNPACK2(lo[c], hi[c], acc[p][c]);
        int ii0 = rowBase + ty * 4 + p * 2;
        float4 r0 = make_float4(__uint_as_float(lo[0]), __uint_as_float(lo[1]),
                                __uint_as_float(lo[2]), __uint_as_float(lo[3]));
        float4 r1 = make_float4(__uint_as_float(hi[0]), __uint_as_float(hi[1]),
                                __uint_as_float(hi[2]), __uint_as_float(hi[3]));
        *reinterpret_cast<float4*>(&g_part[z][ii0 * BB + gj])       = r0;
        *reinterpret_cast<float4*>(&g_part[z][(ii0 + 1) * BB + gj]) = r1;
    }
}

// ---------------------------------------------------------------------------
// Kernel 2: triplets over compacted active anchors. 512 blocks x 128 thr;
// slots past nact only join the done-counter. Ballot compaction of negatives.
// ---------------------------------------------------------------------------
__global__ __launch_bounds__(128) void k_tri(float* __restrict__ out) {
    __shared__ float    nd[BB];
    __shared__ int      nn;
    __shared__ float    wsum[4];
    __shared__ unsigned wcnt[4];

    int ii   = blockIdx.x;
    int tid  = threadIdx.x;
    int lane = tid & 31;
    int wid  = tid >> 5;
    int nact = g_nact;

    float    lsum = 0.0f;
    unsigned lcnt = 0u;

    if (ii < nact) {
        int i = g_act[ii];
        unsigned mi = g_lab[i];
        float    ni = g_norm[i];
        if (tid == 0) nn = 0;

        float dv[4];
        int   pf[4];
#pragma unroll
        for (int s = 0; s < 4; ++s) {
            int j = s * 128 + tid;
            const float* p = &g_part[0][ii * BB + j];
            float G  = ((p[0] + p[BB * BB]) + p[2 * BB * BB]) + p[3 * BB * BB];
            float sq = ni + g_norm[j] - 2.0f * G;
            dv[s] = (sq > 0.0f) ? sqrtf(sq) : 0.0f;
            pf[s] = (g_lab[j] & mi) != 0u;
        }
        __syncthreads();

#pragma unroll
        for (int s = 0; s < 4; ++s) {
            unsigned bal = __ballot_sync(0xffffffffu, !pf[s]);
            if (bal) {
                int base = 0;
                if (lane == 0) base = atomicAdd(&nn, __popc(bal));
                base = __shfl_sync(0xffffffffu, base, 0);
                if (!pf[s]) {
                    int r = __popc(bal & ((1u << lane) - 1u));
                    nd[base + r] = dv[s];
                }
            }
        }
        __syncthreads();

        int N = nn;
        if (N > 0) {
#pragma unroll
            for (int s = 0; s < 4; ++s) {
                if (pf[s]) {
                    float dj = dv[s];
                    for (int k = 0; k < N; ++k) {
                        float v = dj - nd[k];
                        if (v > 1e-16f) { lsum += v; lcnt++; }
                    }
                }
            }
        }

#pragma unroll
        for (int off = 16; off; off >>= 1) {
            lsum += __shfl_down_sync(0xffffffffu, lsum, off);
            lcnt += __shfl_down_sync(0xffffffffu, lcnt, off);
        }
        if (lane == 0) { wsum[wid] = lsum; wcnt[wid] = lcnt; }
        __syncthreads();
        if (wid == 0) {
            lsum = (lane < 4) ? wsum[lane] : 0.0f;
            lcnt = (lane < 4) ? wcnt[lane] : 0u;
#pragma unroll
            for (int off = 2; off; off >>= 1) {
                lsum += __shfl_down_sync(0xffffffffu, lsum, off);
                lcnt += __shfl_down_sync(0xffffffffu, lcnt, off);
            }
        }
    }

    // every block (active or not) participates in completion + finalize
    if (tid == 0) {
        if (lcnt != 0u || lsum != 0.0f) {
            atomicAdd(&g_sum, lsum);
            atomicAdd(&g_cnt, lcnt);
        }
        __threadfence();
        unsigned prev = atomicAdd(&g_done, 1u);
        if (prev == (unsigned)(BB - 1)) {
            float    s = *((volatile float*)&g_sum);
            unsigned c = *((volatile unsigned*)&g_cnt);
            out[0] = (float)((double)s / ((double)c + 1e-16));
            g_sum = 0.0f; g_cnt = 0u; g_done = 0u;  // reset for replay
        }
    }
}

extern "C" void kernel_launch(void* const* d_in, const int* in_sizes, int n_in,
                              void* d_out, int out_size) {
    const float* src = (const float*)d_in[0];  // (B, D) float32
    const int*   lab = (const int*)d_in[1];    // (B, L) int32

    k_prep<<<33, 512>>>(src, lab);
    dim3 grid(BB / TC, BB / TR, SPLITS);       // 8 x 16 x 4 = 512 slots
    k_gram<<<grid, 128>>>(src);
    k_tri<<<BB, 128>>>((float*)d_out);
}

// round 16
// speedup vs baseline: 1.2164x; 1.2164x over previous
#include <cuda_runtime.h>
#include <math.h>
#include <stdint.h>

#define BB 512
#define DD 512
#define LL 24

#define TR 32               // tile rows (active anchors)
#define TC 64               // tile cols
#define KC 16
#define SPLITS 4
#define KSP (DD / SPLITS)   // 128
#define NCHUNK (KSP / KC)   // 8

// Scratch (device globals — no allocations allowed)
__device__ float        g_part[SPLITS][BB * BB];  // [z][ii_compact * BB + j]
__device__ float        g_norm[BB];
__device__ unsigned int g_lab[BB];
__device__ int          g_act[BB];
__device__ int          g_nact;
__device__ float        g_sum;
__device__ unsigned int g_cnt;
__device__ unsigned int g_done;

// Packed dual-FP32 FMA (Blackwell f32x2; base-family PTX, sm_100+)
#define FMA2(acc, a, b) \
    asm("fma.rn.f32x2 %0, %1, %2, %0;" : "+l"(acc) : "l"(a), "l"(b))
#define PACK_DUP(out, f) \
    asm("mov.b64 %0, {%1, %1};" : "=l"(out) : "r"(__float_as_uint(f)))
#define UNPACK2(lo, hi, in) \
    asm("mov.b64 {%0, %1}, %2;" : "=r"(lo), "=r"(hi) : "l"(in))

// ---------------------------------------------------------------------------
// Kernel 0: prep. Block 0: pack label masks, find active anchors (those with
// >=1 negative) via a BRANCH-FREE unrolled OR-scan (the round-15 version had
// a load-dependent break -> serialized ~30cyc/iter), then build a
// deterministic sorted compact list via ballot scan.
// Blocks 1..32: row norms (16 rows each, warp per row).
// ---------------------------------------------------------------------------
__global__ __launch_bounds__(512) void k_prep(const float* __restrict__ X,
                                              const int* __restrict__ labels) {
    int b = blockIdx.x;
    int tid = threadIdx.x;
    int lane = tid & 31, w = tid >> 5;

    if (b == 0) {
        __shared__ unsigned labs[BB];
        __shared__ int wcount[16];
        unsigned m = 0u;
#pragma unroll
        for (int l = 0; l < LL; ++l)
            if (labels[tid * LL + l] != 0) m |= (1u << l);
        labs[tid] = m;
        g_lab[tid] = m;
        if (tid == 0) { g_sum = 0.0f; g_cnt = 0u; g_done = 0u; }
        __syncthreads();

        // branch-free scan: loads pipeline (no dependent branch per LDS)
        unsigned any = 0u;
#pragma unroll 8
        for (int j = 0; j < BB; ++j)
            any |= (unsigned)((labs[j] & m) == 0u);
        bool act = (any != 0u);

        unsigned bal = __ballot_sync(0xffffffffu, act);
        if (lane == 0) wcount[w] = __popc(bal);
        __syncthreads();
        int base = 0;
        for (int ww = 0; ww < w; ++ww) base += wcount[ww];
        if (act) {
            int r = __popc(bal & ((1u << lane) - 1u));
            g_act[base + r] = tid;
        }
        if (tid == 511) {
            int tot = 0;
            for (int ww = 0; ww < 16; ++ww) tot += wcount[ww];
            g_nact = tot;
        }
    } else {
        int row = (b - 1) * 16 + w;           // blocks 1..32, 16 rows each
        const float4* xr = reinterpret_cast<const float4*>(X + row * DD);
        float s = 0.0f;
#pragma unroll
        for (int t = 0; t < 4; ++t) {
            float4 v = xr[t * 32 + lane];
            s += v.x * v.x + v.y * v.y + v.z * v.z + v.w * v.w;
        }
#pragma unroll
        for (int off = 16; off; off >>= 1)
            s += __shfl_down_sync(0xffffffffu, s, off);
        if (lane == 0) g_norm[row] = s;
    }
}

// ---------------------------------------------------------------------------
// Kernel 1: Gram partials for ACTIVE anchor rows only. Tile 32 (gathered
// active rows) x 64 cols, K-split 4. Grid (8,16,4)=512 slots; slots past
// nact exit immediately (~0.4x survive). Microtile 4 rows (2 pairs) x 4 cols
// = 8 FFMA2/kk, proven staging/prefetch pattern.
// ---------------------------------------------------------------------------
__global__ __launch_bounds__(128) void k_gram(const float* __restrict__ X) {
    int nact = g_nact;
    int rowBase = blockIdx.y * TR;
    if (rowBase >= nact) return;

    __shared__ float As[2][KC][TR + 4];
    __shared__ float Bs[2][KC][TC + 4];

    int tid = threadIdx.x;
    int ty = tid >> 4;          // 0..7  : 4 rows (2 pairs)
    int tx = tid & 15;          // 0..15 : 4 cols
    int colBase = blockIdx.x * TC;
    int z       = blockIdx.z;
    int kBase   = z * KSP;

    // staging: A = 128 float4 (1/thread), B = 256 float4 (2/thread)
    int ar  = tid >> 2;                 // 0..31
    int kg  = (tid & 3) * 4;
    int aidx = rowBase + ar;
    int asrc = (aidx < nact) ? g_act[aidx] : g_act[0];
    const float* Arow  = &X[asrc * DD + kBase];
    const float* Brow0 = &X[(colBase + ar) * DD + kBase];
    const float* Brow1 = &X[(colBase + ar + 32) * DD + kBase];

    unsigned long long acc[2][4];
#pragma unroll
    for (int p = 0; p < 2; ++p)
#pragma unroll
        for (int c = 0; c < 4; ++c) acc[p][c] = 0ull;

    float4 pa  = *reinterpret_cast<const float4*>(&Arow[kg]);
    float4 pb0 = *reinterpret_cast<const float4*>(&Brow0[kg]);
    float4 pb1 = *reinterpret_cast<const float4*>(&Brow1[kg]);

#pragma unroll
    for (int c = 0; c < NCHUNK; ++c) {
        int buf = c & 1;
        As[buf][kg + 0][ar] = pa.x;  As[buf][kg + 1][ar] = pa.y;
        As[buf][kg + 2][ar] = pa.z;  As[buf][kg + 3][ar] = pa.w;
        Bs[buf][kg + 0][ar] = pb0.x; Bs[buf][kg + 1][ar] = pb0.y;
        Bs[buf][kg + 2][ar] = pb0.z; Bs[buf][kg + 3][ar] = pb0.w;
        Bs[buf][kg + 0][ar + 32] = pb1.x; Bs[buf][kg + 1][ar + 32] = pb1.y;
        Bs[buf][kg + 2][ar + 32] = pb1.z; Bs[buf][kg + 3][ar + 32] = pb1.w;
        __syncthreads();

        if (c + 1 < NCHUNK) {
            int ko = (c + 1) * KC;
            pa  = *reinterpret_cast<const float4*>(&Arow[ko + kg]);
            pb0 = *reinterpret_cast<const float4*>(&Brow0[ko + kg]);
            pb1 = *reinterpret_cast<const float4*>(&Brow1[ko + kg]);
        }

#pragma unroll
        for (int kk = 0; kk < KC; ++kk) {
            ulonglong2 a2 =
                *reinterpret_cast<const ulonglong2*>(&As[buf][kk][ty * 4]);
            float4 b4 = *reinterpret_cast<const float4*>(&Bs[buf][kk][tx * 4]);
            unsigned long long B0, B1, B2, B3;
            PACK_DUP(B0, b4.x); PACK_DUP(B1, b4.y);
            PACK_DUP(B2, b4.z); PACK_DUP(B3, b4.w);
            FMA2(acc[0][0], a2.x, B0); FMA2(acc[0][1], a2.x, B1);
            FMA2(acc[0][2], a2.x, B2); FMA2(acc[0][3], a2.x, B3);
            FMA2(acc[1][0], a2.y, B0); FMA2(acc[1][1], a2.y, B1);
            FMA2(acc[1][2], a2.y, B2); FMA2(acc[1][3], a2.y, B3);
        }
        __syncthreads();
    }

    // epilogue: 2 row-pairs x 4 cols (compacted row index ii)
    int gj = colBase + tx * 4;
#pragma unroll
    for (int p = 0; p < 2; ++p) {
        unsigned lo[4], hi[4];
#pragma unroll
        for (int c = 0; c < 4; ++c) UNPACK2(lo[c], hi[c], acc[p][c]);
        int ii0 = rowBase + ty * 4 + p * 2;
        float4 r0 = make_float4(__uint_as_float(lo[0]), __uint_as_float(lo[1]),
                                __uint_as_float(lo[2]), __uint_as_float(lo[3]));
        float4 r1 = make_float4(__uint_as_float(hi[0]), __uint_as_float(hi[1]),
                                __uint_as_float(hi[2]), __uint_as_float(hi[3]));
        *reinterpret_cast<float4*>(&g_part[z][ii0 * BB + gj])       = r0;
        *reinterpret_cast<float4*>(&g_part[z][(ii0 + 1) * BB + gj]) = r1;
    }
}

// ---------------------------------------------------------------------------
// Kernel 2: triplets over compacted active anchors. 512 blocks x 128 thr;
// slots past nact only join the done-counter. Ballot compaction of negatives.
// ---------------------------------------------------------------------------
__global__ __launch_bounds__(128) void k_tri(float* __restrict__ out) {
    __shared__ float    nd[BB];
    __shared__ int      nn;
    __shared__ float    wsum[4];
    __shared__ unsigned wcnt[4];

    int ii   = blockIdx.x;
    int tid  = threadIdx.x;
    int lane = tid & 31;
    int wid  = tid >> 5;
    int nact = g_nact;

    float    lsum = 0.0f;
    unsigned lcnt = 0u;

    if (ii < nact) {
        int i = g_act[ii];
        unsigned mi = g_lab[i];
        float    ni = g_norm[i];
        if (tid == 0) nn = 0;

        float dv[4];
        int   pf[4];
#pragma unroll
        for (int s = 0; s < 4; ++s) {
            int j = s * 128 + tid;
            const float* p = &g_part[0][ii * BB + j];
            float G  = ((p[0] + p[BB * BB]) + p[2 * BB * BB]) + p[3 * BB * BB];
            float sq = ni + g_norm[j] - 2.0f * G;
            dv[s] = (sq > 0.0f) ? sqrtf(sq) : 0.0f;
            pf[s] = (g_lab[j] & mi) != 0u;
        }
        __syncthreads();

#pragma unroll
        for (int s = 0; s < 4; ++s) {
            unsigned bal = __ballot_sync(0xffffffffu, !pf[s]);
            if (bal) {
                int base = 0;
                if (lane == 0) base = atomicAdd(&nn, __popc(bal));
                base = __shfl_sync(0xffffffffu, base, 0);
                if (!pf[s]) {
                    int r = __popc(bal & ((1u << lane) - 1u));
                    nd[base + r] = dv[s];
                }
            }
        }
        __syncthreads();

        int N = nn;
        if (N > 0) {
#pragma unroll
            for (int s = 0; s < 4; ++s) {
                if (pf[s]) {
                    float dj = dv[s];
                    for (int k = 0; k < N; ++k) {
                        float v = dj - nd[k];
                        if (v > 1e-16f) { lsum += v; lcnt++; }
                    }
                }
            }
        }

#pragma unroll
        for (int off = 16; off; off >>= 1) {
            lsum += __shfl_down_sync(0xffffffffu, lsum, off);
            lcnt += __shfl_down_sync(0xffffffffu, lcnt, off);
        }
        if (lane == 0) { wsum[wid] = lsum; wcnt[wid] = lcnt; }
        __syncthreads();
        if (wid == 0) {
            lsum = (lane < 4) ? wsum[lane] : 0.0f;
            lcnt = (lane < 4) ? wcnt[lane] : 0u;
#pragma unroll
            for (int off = 2; off; off >>= 1) {
                lsum += __shfl_down_sync(0xffffffffu, lsum, off);
                lcnt += __shfl_down_sync(0xffffffffu, lcnt, off);
            }
        }
    }

    // every block (active or not) participates in completion + finalize
    if (tid == 0) {
        if (lcnt != 0u || lsum != 0.0f) {
            atomicAdd(&g_sum, lsum);
            atomicAdd(&g_cnt, lcnt);
        }
        __threadfence();
        unsigned prev = atomicAdd(&g_done, 1u);
        if (prev == (unsigned)(BB - 1)) {
            float    s = *((volatile float*)&g_sum);
            unsigned c = *((volatile unsigned*)&g_cnt);
            out[0] = (float)((double)s / ((double)c + 1e-16));
            g_sum = 0.0f; g_cnt = 0u; g_done = 0u;  // reset for replay
        }
    }
}

extern "C" void kernel_launch(void* const* d_in, const int* in_sizes, int n_in,
                              void* d_out, int out_size) {
    const float* src = (const float*)d_in[0];  // (B, D) float32
    const int*   lab = (const int*)d_in[1];    // (B, L) int32

    k_prep<<<33, 512>>>(src, lab);
    dim3 grid(BB / TC, BB / TR, SPLITS);       // 8 x 16 x 4 = 512 slots
    k_gram<<<grid, 128>>>(src);
    k_tri<<<BB, 128>>>((float*)d_out);
}

// round 17
// speedup vs baseline: 1.3265x; 1.0906x over previous
#include <cuda_runtime.h>
#include <math.h>
#include <stdint.h>

#define BB 512
#define DD 512
#define LL 24

#define TR 32               // tile rows (active anchors)
#define TC 64               // tile cols
#define KC 16
#define SPLITS 4
#define KSP (DD / SPLITS)   // 128
#define NCHUNK (KSP / KC)   // 8

// Scratch (device globals — no allocations allowed)
__device__ float        g_part[SPLITS][BB * BB];  // [z][ii_compact * BB + j]
__device__ float        g_norm[BB];
__device__ unsigned int g_lab[BB];
__device__ int          g_act[BB];
__device__ int          g_nact;
__device__ float        g_sum;
__device__ unsigned int g_cnt;
__device__ unsigned int g_done;

// Packed dual-FP32 FMA (Blackwell f32x2; base-family PTX, sm_100+)
#define FMA2(acc, a, b) \
    asm("fma.rn.f32x2 %0, %1, %2, %0;" : "+l"(acc) : "l"(a), "l"(b))
#define PACK_DUP(out, f) \
    asm("mov.b64 %0, {%1, %1};" : "=l"(out) : "r"(__float_as_uint(f)))
#define UNPACK2(lo, hi, in) \
    asm("mov.b64 {%0, %1}, %2;" : "=r"(lo), "=r"(hi) : "l"(in))

// ---------------------------------------------------------------------------
// Kernel 0: prep. Block 0: pack label masks via WARP BALLOT (coalesced row
// loads: lanes 0..23 read the row's 24 consecutive ints; mask = ballot) —
// the round-16 version did 24 strided LDGs/thread = 32 wavefronts each.
// Activity scan reads labs as uint4 (4 masks per broadcast LDS.128).
// Deterministic sorted compact list via ballot scan.
// Blocks 1..32: row norms (16 rows each, warp per row).
// ---------------------------------------------------------------------------
__global__ __launch_bounds__(512) void k_prep(const float* __restrict__ X,
                                              const int* __restrict__ labels) {
    int b = blockIdx.x;
    int tid = threadIdx.x;
    int lane = tid & 31, w = tid >> 5;

    if (b == 0) {
        __shared__ unsigned labs[BB];
        __shared__ int wcount[16];
        if (tid == 0) { g_sum = 0.0f; g_cnt = 0u; g_done = 0u; }

        // warp w packs rows w*32 .. w*32+31 (coalesced + ballot)
#pragma unroll 4
        for (int r = 0; r < 32; ++r) {
            int row = w * 32 + r;
            int v = (lane < LL) ? labels[row * LL + lane] : 0;
            unsigned mask = __ballot_sync(0xffffffffu, v != 0);
            if (lane == 0) { labs[row] = mask; g_lab[row] = mask; }
        }
        __syncthreads();

        unsigned m = labs[tid];
        // vectorized branch-free scan: 128 broadcast LDS.128, 4 masks each
        unsigned any = 0u;
        const uint4* l4 = reinterpret_cast<const uint4*>(labs);
#pragma unroll 8
        for (int j = 0; j < BB / 4; ++j) {
            uint4 v = l4[j];
            any |= (unsigned)((v.x & m) == 0u) | (unsigned)((v.y & m) == 0u)
                 | (unsigned)((v.z & m) == 0u) | (unsigned)((v.w & m) == 0u);
        }
        bool act = (any != 0u);

        unsigned bal = __ballot_sync(0xffffffffu, act);
        if (lane == 0) wcount[w] = __popc(bal);
        __syncthreads();
        int base = 0;
        for (int ww = 0; ww < w; ++ww) base += wcount[ww];
        if (act) {
            int r = __popc(bal & ((1u << lane) - 1u));
            g_act[base + r] = tid;
        }
        if (tid == 511) {
            int tot = 0;
            for (int ww = 0; ww < 16; ++ww) tot += wcount[ww];
            g_nact = tot;
        }
    } else {
        int row = (b - 1) * 16 + w;           // blocks 1..32, 16 rows each
        const float4* xr = reinterpret_cast<const float4*>(X + row * DD);
        float s = 0.0f;
#pragma unroll
        for (int t = 0; t < 4; ++t) {
            float4 v = xr[t * 32 + lane];
            s += v.x * v.x + v.y * v.y + v.z * v.z + v.w * v.w;
        }
#pragma unroll
        for (int off = 16; off; off >>= 1)
            s += __shfl_down_sync(0xffffffffu, s, off);
        if (lane == 0) g_norm[row] = s;
    }
}

// ---------------------------------------------------------------------------
// Kernel 1: Gram partials for ACTIVE anchor rows only. Tile 32 (gathered
// active rows) x 64 cols, K-split 4. Grid (8,16,4)=512 slots; slots past
// nact exit immediately (~0.4x survive). Microtile 4 rows (2 pairs) x 4 cols
// = 8 FFMA2/kk, proven staging/prefetch pattern.
// ---------------------------------------------------------------------------
__global__ __launch_bounds__(128) void k_gram(const float* __restrict__ X) {
    int nact = g_nact;
    int rowBase = blockIdx.y * TR;
    if (rowBase >= nact) return;

    __shared__ float As[2][KC][TR + 4];
    __shared__ float Bs[2][KC][TC + 4];

    int tid = threadIdx.x;
    int ty = tid >> 4;          // 0..7  : 4 rows (2 pairs)
    int tx = tid & 15;          // 0..15 : 4 cols
    int colBase = blockIdx.x * TC;
    int z       = blockIdx.z;
    int kBase   = z * KSP;

    // staging: A = 128 float4 (1/thread), B = 256 float4 (2/thread)
    int ar  = tid >> 2;                 // 0..31
    int kg  = (tid & 3) * 4;
    int aidx = rowBase + ar;
    int asrc = (aidx < nact) ? g_act[aidx] : g_act[0];
    const float* Arow  = &X[asrc * DD + kBase];
    const float* Brow0 = &X[(colBase + ar) * DD + kBase];
    const float* Brow1 = &X[(colBase + ar + 32) * DD + kBase];

    unsigned long long acc[2][4];
#pragma unroll
    for (int p = 0; p < 2; ++p)
#pragma unroll
        for (int c = 0; c < 4; ++c) acc[p][c] = 0ull;

    float4 pa  = *reinterpret_cast<const float4*>(&Arow[kg]);
    float4 pb0 = *reinterpret_cast<const float4*>(&Brow0[kg]);
    float4 pb1 = *reinterpret_cast<const float4*>(&Brow1[kg]);

#pragma unroll
    for (int c = 0; c < NCHUNK; ++c) {
        int buf = c & 1;
        As[buf][kg + 0][ar] = pa.x;  As[buf][kg + 1][ar] = pa.y;
        As[buf][kg + 2][ar] = pa.z;  As[buf][kg + 3][ar] = pa.w;
        Bs[buf][kg + 0][ar] = pb0.x; Bs[buf][kg + 1][ar] = pb0.y;
        Bs[buf][kg + 2][ar] = pb0.z; Bs[buf][kg + 3][ar] = pb0.w;
        Bs[buf][kg + 0][ar + 32] = pb1.x; Bs[buf][kg + 1][ar + 32] = pb1.y;
        Bs[buf][kg + 2][ar + 32] = pb1.z; Bs[buf][kg + 3][ar + 32] = pb1.w;
        __syncthreads();

        if (c + 1 < NCHUNK) {
            int ko = (c + 1) * KC;
            pa  = *reinterpret_cast<const float4*>(&Arow[ko + kg]);
            pb0 = *reinterpret_cast<const float4*>(&Brow0[ko + kg]);
            pb1 = *reinterpret_cast<const float4*>(&Brow1[ko + kg]);
        }

#pragma unroll
        for (int kk = 0; kk < KC; ++kk) {
            ulonglong2 a2 =
                *reinterpret_cast<const ulonglong2*>(&As[buf][kk][ty * 4]);
            float4 b4 = *reinterpret_cast<const float4*>(&Bs[buf][kk][tx * 4]);
            unsigned long long B0, B1, B2, B3;
            PACK_DUP(B0, b4.x); PACK_DUP(B1, b4.y);
            PACK_DUP(B2, b4.z); PACK_DUP(B3, b4.w);
            FMA2(acc[0][0], a2.x, B0); FMA2(acc[0][1], a2.x, B1);
            FMA2(acc[0][2], a2.x, B2); FMA2(acc[0][3], a2.x, B3);
            FMA2(acc[1][0], a2.y, B0); FMA2(acc[1][1], a2.y, B1);
            FMA2(acc[1][2], a2.y, B2); FMA2(acc[1][3], a2.y, B3);
        }
        __syncthreads();
    }

    // epilogue: 2 row-pairs x 4 cols (compacted row index ii)
    int gj = colBase + tx * 4;
#pragma unroll
    for (int p = 0; p < 2; ++p) {
        unsigned lo[4], hi[4];
#pragma unroll
        for (int c = 0; c < 4; ++c) UNPACK2(lo[c], hi[c], acc[p][c]);
        int ii0 = rowBase + ty * 4 + p * 2;
        float4 r0 = make_float4(__uint_as_float(lo[0]), __uint_as_float(lo[1]),
                                __uint_as_float(lo[2]), __uint_as_float(lo[3]));
        float4 r1 = make_float4(__uint_as_float(hi[0]), __uint_as_float(hi[1]),
                                __uint_as_float(hi[2]), __uint_as_float(hi[3]));
        *reinterpret_cast<float4*>(&g_part[z][ii0 * BB + gj])       = r0;
        *reinterpret_cast<float4*>(&g_part[z][(ii0 + 1) * BB + gj]) = r1;
    }
}

// ---------------------------------------------------------------------------
// Kernel 2: triplets over compacted active anchors. 512 blocks x 128 thr;
// slots past nact only join the done-counter. Ballot compaction of negatives.
// ---------------------------------------------------------------------------
__global__ __launch_bounds__(128) void k_tri(float* __restrict__ out) {
    __shared__ float    nd[BB];
    __shared__ int      nn;
    __shared__ float    wsum[4];
    __shared__ unsigned wcnt[4];

    int ii   = blockIdx.x;
    int tid  = threadIdx.x;
    int lane = tid & 31;
    int wid  = tid >> 5;
    int nact = g_nact;

    float    lsum = 0.0f;
    unsigned lcnt = 0u;

    if (ii < nact) {
        int i = g_act[ii];
        unsigned mi = g_lab[i];
        float    ni = g_norm[i];
        if (tid == 0) nn = 0;

        float dv[4];
        int   pf[4];
#pragma unroll
        for (int s = 0; s < 4; ++s) {
            int j = s * 128 + tid;
            const float* p = &g_part[0][ii * BB + j];
            float G  = ((p[0] + p[BB * BB]) + p[2 * BB * BB]) + p[3 * BB * BB];
            float sq = ni + g_norm[j] - 2.0f * G;
            dv[s] = (sq > 0.0f) ? sqrtf(sq) : 0.0f;
            pf[s] = (g_lab[j] & mi) != 0u;
        }
        __syncthreads();

#pragma unroll
        for (int s = 0; s < 4; ++s) {
            unsigned bal = __ballot_sync(0xffffffffu, !pf[s]);
            if (bal) {
                int base = 0;
                if (lane == 0) base = atomicAdd(&nn, __popc(bal));
                base = __shfl_sync(0xffffffffu, base, 0);
                if (!pf[s]) {
                    int r = __popc(bal & ((1u << lane) - 1u));
                    nd[base + r] = dv[s];
                }
            }
        }
        __syncthreads();

        int N = nn;
        if (N > 0) {
#pragma unroll
            for (int s = 0; s < 4; ++s) {
                if (pf[s]) {
                    float dj = dv[s];
                    for (int k = 0; k < N; ++k) {
                        float v = dj - nd[k];
                        if (v > 1e-16f) { lsum += v; lcnt++; }
                    }
                }
            }
        }

#pragma unroll
        for (int off = 16; off; off >>= 1) {
            lsum += __shfl_down_sync(0xffffffffu, lsum, off);
            lcnt += __shfl_down_sync(0xffffffffu, lcnt, off);
        }
        if (lane == 0) { wsum[wid] = lsum; wcnt[wid] = lcnt; }
        __syncthreads();
        if (wid == 0) {
            lsum = (lane < 4) ? wsum[lane] : 0.0f;
            lcnt = (lane < 4) ? wcnt[lane] : 0u;
#pragma unroll
            for (int off = 2; off; off >>= 1) {
                lsum += __shfl_down_sync(0xffffffffu, lsum, off);
                lcnt += __shfl_down_sync(0xffffffffu, lcnt, off);
            }
        }
    }

    // every block (active or not) participates in completion + finalize
    if (tid == 0) {
        if (lcnt != 0u || lsum != 0.0f) {
            atomicAdd(&g_sum, lsum);
            atomicAdd(&g_cnt, lcnt);
        }
        __threadfence();
        unsigned prev = atomicAdd(&g_done, 1u);
        if (prev == (unsigned)(BB - 1)) {
            float    s = *((volatile float*)&g_sum);
            unsigned c = *((volatile unsigned*)&g_cnt);
            out[0] = (float)((double)s / ((double)c + 1e-16));
            g_sum = 0.0f; g_cnt = 0u; g_done = 0u;  // reset for replay
        }
    }
}

extern "C" void kernel_launch(void* const* d_in, const int* in_sizes, int n_in,
                              void* d_out, int out_size) {
    const float* src = (const float*)d_in[0];  // (B, D) float32
    const int*   lab = (const int*)d_in[1];    // (B, L) int32

    k_prep<<<33, 512>>>(src, lab);
    dim3 grid(BB / TC, BB / TR, SPLITS);       // 8 x 16 x 4 = 512 slots
    k_gram<<<grid, 128>>>(src);
    k_tri<<<BB, 128>>>((float*)d_out);
}